// round 17
// baseline (speedup 1.0000x reference)
#include <cuda_runtime.h>
#include <cuda_bf16.h>
#include <stdint.h>

#define BB 4
#define NN 4096
#define CC 256
#define MM 2048
#define TAU_F 0.4f
#define LOG2E 1.4426950408889634f

#define TMC 64
#define NCH (MM / TMC)          // 32 chunks
#define TILE_N 128
#define NTILES (NN / TILE_N)    // 32 tiles
#define NTHR 256                // 8 warps
#define LPAD 264                // halves per L row (528 B = 33*16B -> conflict-free LDSM)

#define SM_LS 0
#define LS_BYTES (TILE_N * LPAD * 2)      // 67584 = 4224 uint4
#define LS_U4 (LS_BYTES / 16)             // 4224
#define SM_GS LS_BYTES                    // 1024-aligned (67584 = 66*1024)
#define GS_BYTES (CC * TMC * 2)           // 32768 per slot, 3 slots
#define SM_GN (SM_GS + 3 * GS_BYTES)      // 165888
#define SMEM_ALLOC (SM_GN + 3 * 256 + 1024)

#define NLBLK (BB * NN / 8)               // 2048 L-blocks (8 rows each)

__device__ __align__(16) __nv_bfloat16 d_Lbf[BB * NN * LPAD];
__device__ __align__(16) __nv_bfloat16 d_Gbf[BB * NCH * CC * TMC];
__device__ float d_rln[BB * NN];   // log2e / (tau * ||l_n||)
__device__ float d_rgn[BB * MM];   // 1 / ||g_m||

// ---------------------------------------------------------------------------
__device__ __forceinline__ uint32_t smem_u32(const void* p) {
    uint32_t a;
    asm("{ .reg .u64 t; cvta.to.shared.u64 t, %1; cvt.u32.u64 %0, t; }" : "=r"(a) : "l"(p));
    return a;
}
__device__ __forceinline__ void ldsm_x4(uint32_t a, uint32_t* r) {
    asm volatile("ldmatrix.sync.aligned.m8n8.x4.shared.b16 {%0,%1,%2,%3}, [%4];"
                 : "=r"(r[0]), "=r"(r[1]), "=r"(r[2]), "=r"(r[3]) : "r"(a));
}
__device__ __forceinline__ void ldsm_x4t(uint32_t a, uint32_t* r) {
    asm volatile("ldmatrix.sync.aligned.m8n8.x4.trans.shared.b16 {%0,%1,%2,%3}, [%4];"
                 : "=r"(r[0]), "=r"(r[1]), "=r"(r[2]), "=r"(r[3]) : "r"(a));
}
__device__ __forceinline__ void mma16816(float* d, const uint32_t* a, uint32_t b0, uint32_t b1) {
    asm volatile("mma.sync.aligned.m16n8k16.row.col.f32.bf16.bf16.f32 "
                 "{%0,%1,%2,%3}, {%4,%5,%6,%7}, {%8,%9}, {%0,%1,%2,%3};"
                 : "+f"(d[0]), "+f"(d[1]), "+f"(d[2]), "+f"(d[3])
                 : "r"(a[0]), "r"(a[1]), "r"(a[2]), "r"(a[3]), "r"(b0), "r"(b1));
}
__device__ __forceinline__ float ex2f(float x) {
    float r; asm("ex2.approx.ftz.f32 %0, %1;" : "=f"(r) : "f"(x)); return r;
}
__device__ __forceinline__ void cpasync16(uint32_t dst, const void* src) {
    asm volatile("cp.async.cg.shared.global [%0], [%1], 16;" :: "r"(dst), "l"(src) : "memory");
}

// ---------------------------------------------------------------------------
// Merged prep: blocks [0,NLBLK) do L (warp per row); blocks [NLBLK, +128) do G
// ---------------------------------------------------------------------------
__global__ __launch_bounds__(256) void prep_kernel(const float* __restrict__ l,
                                                   const float* __restrict__ g) {
    __shared__ float2 part[8][32];
    if (blockIdx.x < NLBLK) {
        const int wid = threadIdx.x >> 5, lane = threadIdx.x & 31;
        const int rowg = blockIdx.x * 8 + wid;               // 0..BB*NN-1
        const float4* src = (const float4*)(l + (size_t)rowg * CC);
        float4 v0 = src[lane * 2];
        float4 v1 = src[lane * 2 + 1];
        float s = fmaf(v0.x, v0.x, fmaf(v0.y, v0.y, fmaf(v0.z, v0.z, v0.w * v0.w)));
        s = fmaf(v1.x, v1.x, fmaf(v1.y, v1.y, fmaf(v1.z, v1.z, fmaf(v1.w, v1.w, s))));
#pragma unroll
        for (int o = 16; o; o >>= 1) s += __shfl_xor_sync(0xffffffffu, s, o);
        uint32_t p0, p1, p2, p3;
        asm("cvt.rn.bf16x2.f32 %0, %1, %2;" : "=r"(p0) : "f"(v0.y), "f"(v0.x));
        asm("cvt.rn.bf16x2.f32 %0, %1, %2;" : "=r"(p1) : "f"(v0.w), "f"(v0.z));
        asm("cvt.rn.bf16x2.f32 %0, %1, %2;" : "=r"(p2) : "f"(v1.y), "f"(v1.x));
        asm("cvt.rn.bf16x2.f32 %0, %1, %2;" : "=r"(p3) : "f"(v1.w), "f"(v1.z));
        uint4* dst = (uint4*)(d_Lbf + (size_t)rowg * LPAD);
        dst[lane] = make_uint4(p0, p1, p2, p3);
        if (lane == 0) d_rln[rowg] = LOG2E / (TAU_F * sqrtf(s));
    } else {
        const int bc = blockIdx.x - NLBLK;                   // 0..127
        const int b = bc >> 5, chunk = bc & 31;
        const int mp = threadIdx.x & 31;                     // m-pair 0..31
        const int cg = threadIdx.x >> 5;                     // warp = c-group
        const int m0 = chunk * TMC + mp * 2;
        const float* gp = g + (size_t)b * CC * MM + m0;
        char* dstb = (char*)(d_Gbf + (size_t)(b * NCH + chunk) * CC * TMC);
        float s0 = 0.f, s1 = 0.f;
#pragma unroll 8
        for (int ci = 0; ci < 32; ci++) {
            int c = cg * 32 + ci;
            float2 v = *(const float2*)(gp + (size_t)c * MM);
            s0 = fmaf(v.x, v.x, s0);
            s1 = fmaf(v.y, v.y, s1);
            uint32_t off = (uint32_t)(c * 128 + mp * 4);
            off ^= (uint32_t)((c & 7) << 4);                 // swizzle bits 4-6 by c&7
            *(__nv_bfloat162*)(dstb + off) = __floats2bfloat162_rn(v.x, v.y);
        }
        part[cg][mp] = make_float2(s0, s1);
        __syncthreads();
        if (threadIdx.x < 32) {
            float a0 = 0.f, a1 = 0.f;
#pragma unroll
            for (int w = 0; w < 8; w++) { a0 += part[w][threadIdx.x].x; a1 += part[w][threadIdx.x].y; }
            const int mg = b * MM + chunk * TMC + threadIdx.x * 2;
            d_rgn[mg]     = rsqrtf(a0);
            d_rgn[mg + 1] = rsqrtf(a1);
        }
    }
}

// ---------------------------------------------------------------------------
// Fused, phase-interleaved: per chunk k the inner loop issues GEMM1(k) and
// GEMM2(k-1) together (independent chains) -> dense crossbar+tensor streams.
// 8 warps x 16 rows = 128-row tile; 3-slot G ring via cp.async.
// ---------------------------------------------------------------------------
__global__ __launch_bounds__(NTHR, 1)
void fused_mma_kernel(const float* __restrict__ l, float* __restrict__ out) {
    extern __shared__ char smraw[];
    char* gb = (char*)(((uintptr_t)smraw + 1023) & ~(uintptr_t)1023);
    const uint32_t base = smem_u32(gb);
    const int t = threadIdx.x, lane = t & 31, wid = t >> 5;
    const int q = lane & 3, lr = lane & 7, lg = lane >> 3;
    const int b = blockIdx.y, tile = blockIdx.x;

    // Stage L tile
    {
        const uint4* s4 = (const uint4*)(d_Lbf + (size_t)(b * NN + tile * TILE_N) * LPAD);
        uint4* d4 = (uint4*)(gb + SM_LS);
        for (int i = t; i < LS_U4; i += NTHR) d4[i] = s4[i];
    }
    // cp.async chunk 0 (group 0) and chunk 1 (group 1)
    const char* gsrc = (const char*)(d_Gbf + (size_t)(b * NCH) * CC * TMC);
    const char* gnsrc = (const char*)(d_rgn + b * MM);
#pragma unroll
    for (int cpre = 0; cpre < 2; cpre++) {
        const char* sg = gsrc + (size_t)cpre * GS_BYTES;
        const uint32_t dg = base + SM_GS + (uint32_t)(cpre * GS_BYTES);
#pragma unroll
        for (int i = 0; i < 8; i++)
            cpasync16(dg + (uint32_t)((t + NTHR * i) * 16), sg + (size_t)(t + NTHR * i) * 16);
        if (t < 16)
            cpasync16(base + SM_GN + (uint32_t)(cpre * 256 + t * 16), gnsrc + cpre * 256 + t * 16);
        asm volatile("cp.async.commit_group;" ::: "memory");
    }

    const int row0 = tile * TILE_N + wid * 16 + (lane >> 2);
    const float rln_lo = d_rln[b * NN + row0];
    const float rln_hi = d_rln[b * NN + row0 + 8];

    const uint32_t aA0 = base + SM_LS
        + (uint32_t)((wid * 16 + (lg & 1) * 8 + lr) * (LPAD * 2)) + (uint32_t)((lg >> 1) * 16);
    uint32_t b1off[4];
#pragma unroll
    for (int pp = 0; pp < 4; pp++)
        b1off[pp] = (uint32_t)(((lg & 1) * 8 + lr) * 128)
                  + ((uint32_t)(pp * 32 + (lg >> 1) * 16) ^ (uint32_t)(lr << 4));
    const uint32_t b2off0 = (uint32_t)(lr * 128) + ((uint32_t)(lg * 16) ^ (uint32_t)(lr << 4));
    const uint32_t b2off1 = (uint32_t)(lr * 128) + ((uint32_t)(64 + lg * 16) ^ (uint32_t)(lr << 4));

    float O[32][4];
#pragma unroll
    for (int nt = 0; nt < 32; nt++) { O[nt][0] = O[nt][1] = O[nt][2] = O[nt][3] = 0.f; }
    float rs_lo = 0.f, rs_hi = 0.f;
    uint32_t afr[4][4];

    // Wait chunk 0 (1 group still in flight), make visible
    asm volatile("cp.async.wait_group 1;" ::: "memory");
    __syncthreads();

    // ---- Peeled k=0: GEMM1(0) + exp(0) -> afr ----
    {
        const uint32_t Gc = base + SM_GS;     // slot 0
        float S[8][4];
#pragma unroll
        for (int p = 0; p < 8; p++) S[p][0] = S[p][1] = S[p][2] = S[p][3] = 0.f;
#pragma unroll
        for (int j = 0; j < 16; j++) {
            uint32_t A[4];
            ldsm_x4(aA0 + (uint32_t)(j * 32), A);
            const uint32_t crow = Gc + (uint32_t)(j * 2048);
#pragma unroll
            for (int pp = 0; pp < 4; pp++) {
                uint32_t B4[4];
                ldsm_x4t(crow + b1off[pp], B4);
                mma16816(S[2 * pp],     A, B4[0], B4[1]);
                mma16816(S[2 * pp + 1], A, B4[2], B4[3]);
            }
        }
        const float* gnp = (const float*)(gb + SM_GN);
#pragma unroll
        for (int p = 0; p < 8; p++) {
            float2 gn2 = *(const float2*)(gnp + p * 8 + q * 2);
            float w0 = ex2f(S[p][0] * rln_lo * gn2.x);
            float w1 = ex2f(S[p][1] * rln_lo * gn2.y);
            float w2 = ex2f(S[p][2] * rln_hi * gn2.x);
            float w3 = ex2f(S[p][3] * rln_hi * gn2.y);
            rs_lo += w0 + w1;
            rs_hi += w2 + w3;
            uint32_t pk01, pk23;
            asm("cvt.rn.bf16x2.f32 %0, %1, %2;" : "=r"(pk01) : "f"(w1), "f"(w0));
            asm("cvt.rn.bf16x2.f32 %0, %1, %2;" : "=r"(pk23) : "f"(w3), "f"(w2));
            afr[p >> 1][(p & 1) * 2 + 0] = pk01;
            afr[p >> 1][(p & 1) * 2 + 1] = pk23;
        }
        asm volatile("cp.async.wait_group 0;" ::: "memory");   // chunk 1 done
        __syncthreads();
        // issue chunk 2 -> slot 2
        {
            const char* sg = gsrc + (size_t)2 * GS_BYTES;
            const uint32_t dg = base + SM_GS + (uint32_t)(2 * GS_BYTES);
#pragma unroll
            for (int i = 0; i < 8; i++)
                cpasync16(dg + (uint32_t)((t + NTHR * i) * 16), sg + (size_t)(t + NTHR * i) * 16);
            if (t < 16)
                cpasync16(base + SM_GN + (uint32_t)(2 * 256 + t * 16), gnsrc + 2 * 256 + t * 16);
            asm volatile("cp.async.commit_group;" ::: "memory");
        }
    }

    // ---- Main loop k=1..NCH-1: GEMM1(k) fused with GEMM2(k-1) ----
    int scur = 1, sprev = 0;
    for (int k = 1; k < NCH; k++) {
        const uint32_t Gc = base + SM_GS + (uint32_t)(scur * GS_BYTES);
        const uint32_t Gp = base + SM_GS + (uint32_t)(sprev * GS_BYTES);
        float S[8][4];
#pragma unroll
        for (int p = 0; p < 8; p++) S[p][0] = S[p][1] = S[p][2] = S[p][3] = 0.f;
#pragma unroll
        for (int j = 0; j < 16; j++) {
            // GEMM1(k) step j
            uint32_t A[4];
            ldsm_x4(aA0 + (uint32_t)(j * 32), A);
            const uint32_t crow = Gc + (uint32_t)(j * 2048);
#pragma unroll
            for (int pp = 0; pp < 4; pp++) {
                uint32_t B4[4];
                ldsm_x4t(crow + b1off[pp], B4);
                mma16816(S[2 * pp],     A, B4[0], B4[1]);
                mma16816(S[2 * pp + 1], A, B4[2], B4[3]);
            }
            // GEMM2(k-1) steps nt=2j, 2j+1 (independent chain: afr + slot prev)
#pragma unroll
            for (int h = 0; h < 2; h++) {
                const int nt = 2 * j + h;
                const uint32_t nb = Gp + (uint32_t)(nt * 1024);
                uint32_t B0[4], B1[4];
                ldsm_x4(nb + b2off0, B0);
                ldsm_x4(nb + b2off1, B1);
                mma16816(O[nt], afr[0], B0[0], B0[1]);
                mma16816(O[nt], afr[1], B0[2], B0[3]);
                mma16816(O[nt], afr[2], B1[0], B1[1]);
                mma16816(O[nt], afr[3], B1[2], B1[3]);
            }
        }
        // exp(k): overwrite afr (its last consumer, GEMM2(k-1), is done)
        const float* gnp = (const float*)(gb + SM_GN + scur * 256);
#pragma unroll
        for (int p = 0; p < 8; p++) {
            float2 gn2 = *(const float2*)(gnp + p * 8 + q * 2);
            float w0 = ex2f(S[p][0] * rln_lo * gn2.x);
            float w1 = ex2f(S[p][1] * rln_lo * gn2.y);
            float w2 = ex2f(S[p][2] * rln_hi * gn2.x);
            float w3 = ex2f(S[p][3] * rln_hi * gn2.y);
            rs_lo += w0 + w1;
            rs_hi += w2 + w3;
            uint32_t pk01, pk23;
            asm("cvt.rn.bf16x2.f32 %0, %1, %2;" : "=r"(pk01) : "f"(w1), "f"(w0));
            asm("cvt.rn.bf16x2.f32 %0, %1, %2;" : "=r"(pk23) : "f"(w3), "f"(w2));
            afr[p >> 1][(p & 1) * 2 + 0] = pk01;
            afr[p >> 1][(p & 1) * 2 + 1] = pk23;
        }
        // chunk k+1 visible to everyone; everyone done reading slot sprev
        asm volatile("cp.async.wait_group 0;" ::: "memory");
        __syncthreads();
        // issue chunk k+2 into the freed slot (== sprev)
        if (k + 2 < NCH) {
            const char* sg = gsrc + (size_t)(k + 2) * GS_BYTES;
            const uint32_t dg = base + SM_GS + (uint32_t)(sprev * GS_BYTES);
#pragma unroll
            for (int i = 0; i < 8; i++)
                cpasync16(dg + (uint32_t)((t + NTHR * i) * 16), sg + (size_t)(t + NTHR * i) * 16);
            if (t < 16)
                cpasync16(base + SM_GN + (uint32_t)(sprev * 256 + t * 16),
                          gnsrc + (size_t)(k + 2) * 256 + t * 16);
            asm volatile("cp.async.commit_group;" ::: "memory");
        }
        sprev = scur;
        scur = (scur == 2) ? 0 : scur + 1;
    }

    // ---- Final GEMM2(NCH-1) from slot (NCH-1)%3 ----
    {
        const uint32_t Gp = base + SM_GS + (uint32_t)(((NCH - 1) % 3) * GS_BYTES);
#pragma unroll
        for (int nt = 0; nt < 32; nt++) {
            const uint32_t nb = Gp + (uint32_t)(nt * 1024);
            uint32_t B0[4], B1[4];
            ldsm_x4(nb + b2off0, B0);
            ldsm_x4(nb + b2off1, B1);
            mma16816(O[nt], afr[0], B0[0], B0[1]);
            mma16816(O[nt], afr[1], B0[2], B0[3]);
            mma16816(O[nt], afr[2], B1[0], B1[1]);
            mma16816(O[nt], afr[3], B1[2], B1[3]);
        }
    }

    // ---- rowsum reduce across the lane quad ----
    rs_lo += __shfl_xor_sync(0xffffffffu, rs_lo, 1);
    rs_lo += __shfl_xor_sync(0xffffffffu, rs_lo, 2);
    rs_hi += __shfl_xor_sync(0xffffffffu, rs_hi, 1);
    rs_hi += __shfl_xor_sync(0xffffffffu, rs_hi, 2);
    const float ri_lo = 1.0f / rs_lo;
    const float ri_hi = 1.0f / rs_hi;

    // ---- Epilogue: out = l + O / rowsum ----
    const float* lrow_lo = l + ((size_t)b * NN + row0) * CC;
    const float* lrow_hi = lrow_lo + 8 * CC;
    float* orow_lo = out + ((size_t)b * NN + row0) * CC;
    float* orow_hi = orow_lo + 8 * CC;
#pragma unroll
    for (int nt = 0; nt < 32; nt++) {
        const int c = nt * 8 + q * 2;
        float2 lv0 = *(const float2*)(lrow_lo + c);
        float2 ov0;
        ov0.x = fmaf(O[nt][0], ri_lo, lv0.x);
        ov0.y = fmaf(O[nt][1], ri_lo, lv0.y);
        *(float2*)(orow_lo + c) = ov0;
        float2 lv1 = *(const float2*)(lrow_hi + c);
        float2 ov1;
        ov1.x = fmaf(O[nt][2], ri_hi, lv1.x);
        ov1.y = fmaf(O[nt][3], ri_hi, lv1.y);
        *(float2*)(orow_hi + c) = ov1;
    }
}

// ---------------------------------------------------------------------------
extern "C" void kernel_launch(void* const* d_in, const int* in_sizes, int n_in,
                              void* d_out, int out_size) {
    (void)in_sizes; (void)n_in; (void)out_size;
    const float* l = (const float*)d_in[0];   // [B, N, C]
    const float* g = (const float*)d_in[1];   // [B, C, M]
    float* out = (float*)d_out;               // [B, N, C]

    cudaFuncSetAttribute(fused_mma_kernel,
                         cudaFuncAttributeMaxDynamicSharedMemorySize, SMEM_ALLOC);

    prep_kernel<<<NLBLK + BB * NCH, 256>>>(l, g);
    fused_mma_kernel<<<dim3(NTILES, BB), NTHR, SMEM_ALLOC>>>(l, out);
}